// round 7
// baseline (speedup 1.0000x reference)
#include <cuda_runtime.h>
#include <cuda_bf16.h>
#include <cstdint>

// ---------------- constants ----------------
#define KP   320           // padded weight K / hidden width (300 -> 320)
#define SH   328           // smem row stride (elems) for H1/H2 tiles (conflict-free)
#define BM   64            // edges per block
#define BK   32            // k-elems per pipeline stage
#define BSTR 40            // Bs smem row stride (elems) (conflict-free)
#define NKC  10            // k chunks per pass (320/32)
#define NSTG 3             // cp.async stages

// ---------------- device scratch ----------------
__device__ __align__(16) __nv_bfloat16 g_W1t[384 * 16];   // W1^T padded [n=384][k=16]
__device__ __align__(16) __nv_bfloat16 g_W2t[384 * KP];   // W2^T padded [n=384][k=320]
__device__ __align__(16) __nv_bfloat16 g_W3t[256 * KP];   // W3^T padded [n=256][k=320]
__device__ double g_acc[2];                               // [0]=sum|y-t|, [1]=KL

__device__ __forceinline__ uint32_t smem_u32(const void* p) {
    return (uint32_t)__cvta_generic_to_shared(p);
}

__global__ void k_zero() { g_acc[0] = 0.0; g_acc[1] = 0.0; }

__global__ void k_base(const float* __restrict__ y, const float* __restrict__ tg, int n) {
    __shared__ float red[8];
    float local = 0.f;
    for (int i = blockIdx.x * blockDim.x + threadIdx.x; i < n; i += gridDim.x * blockDim.x)
        local += fabsf(y[i] - tg[i]);
    int lane = threadIdx.x & 31, warp = threadIdx.x >> 5;
    #pragma unroll
    for (int o = 16; o > 0; o >>= 1) local += __shfl_xor_sync(0xffffffffu, local, o);
    if (lane == 0) red[warp] = local;
    __syncthreads();
    if (threadIdx.x < 8) {
        float v = red[threadIdx.x];
        #pragma unroll
        for (int o = 4; o > 0; o >>= 1) v += __shfl_xor_sync(0xffu, v, o);
        if (threadIdx.x == 0) atomicAdd(&g_acc[0], (double)v);
    }
}

__global__ void k_prep_w(const float* __restrict__ W1,
                         const float* __restrict__ W2,
                         const float* __restrict__ W3) {
    int i = blockIdx.x * blockDim.x + threadIdx.x;
    if (i < 384 * 16) {
        int n = i / 16, k = i % 16;
        g_W1t[i] = __float2bfloat16((n < 300 && k < 12) ? W1[k * 300 + n] : 0.f);
    }
    if (i < 384 * KP) {
        int n = i / KP, k = i % KP;
        g_W2t[i] = __float2bfloat16((n < 300 && k < 300) ? W2[k * 300 + n] : 0.f);
    }
    if (i < 256 * KP) {
        int n = i / KP, k = i % KP;
        g_W3t[i] = __float2bfloat16((n < 200 && k < 300) ? W3[k * 200 + n] : 0.f);
    }
}

// ---------------- fully fused edge pipeline (128 threads, 2 CTAs/SM) ----------------
// smem (dynamic, ~114.7 KB):
//   H1  : 64*SH bf16           41984 B
//   H2  : 64*SH bf16           41984 B
//   Bs  : 3*128*BSTR bf16      30720 B   (also hosts W1s+Es before stage 2)
//   red : 4 f32
#define OFF_H1   0
#define OFF_H2   (64 * SH)                 // elems
#define OFF_BS   (2 * 64 * SH)             // elems
#define OFF_W1S  OFF_BS                    // union: W1s = first 12288 B of Bs
#define OFF_ES   (OFF_BS + 384 * 16)       // union: Es after W1s (2048 B)
#define ELEMS_BF (2 * 64 * SH + NSTG * 128 * BSTR)
#define SMEM_BYTES (ELEMS_BF * 2 + 16)

__global__ __launch_bounds__(128, 2)
void k_fused(const float* __restrict__ x,
             const int*   __restrict__ ei,
             const float* __restrict__ b1,
             const float* __restrict__ b2,
             const float* __restrict__ b3,
             int nEdges) {
    extern __shared__ __align__(16) char smem_raw[];
    __nv_bfloat16* base = (__nv_bfloat16*)smem_raw;
    __nv_bfloat16* H1  = base + OFF_H1;
    __nv_bfloat16* H2  = base + OFF_H2;
    __nv_bfloat16* Bs  = base + OFF_BS;
    __nv_bfloat16* W1s = base + OFF_W1S;
    __nv_bfloat16* Es  = base + OFF_ES;
    float* red = (float*)(base + ELEMS_BF);

    const int t = threadIdx.x;
    const int lane = t & 31, warp = t >> 5;    // 4 warps
    const int mBase = blockIdx.x * BM;
    const int wn = warp * 32;                  // warp grid 1m x 4n, warp tile 64x32
    const int g = lane >> 2, q = lane & 3;

    // ---- stage 0: weights/edge gather into smem ----
    {
        const uint4* src = (const uint4*)g_W1t;
        uint4* dst = (uint4*)W1s;
        for (int i = t; i < 768; i += 128) dst[i] = src[i];
    }
    {
        int el = t >> 1, half = t & 1;
        int e = mBase + el;
        __nv_bfloat16* row = Es + el * 16 + half * 6;
        float v[6] = {0.f, 0.f, 0.f, 0.f, 0.f, 0.f};
        if (e < nEdges) {
            int node = ei[half ? (size_t)nEdges + e : (size_t)e];
            const float* xp = x + (size_t)node * 6;
            float2 a0 = *(const float2*)xp;
            float2 a1 = *(const float2*)(xp + 2);
            float2 a2 = *(const float2*)(xp + 4);
            v[0] = a0.x; v[1] = a0.y; v[2] = a1.x; v[3] = a1.y; v[4] = a2.x; v[5] = a2.y;
        }
        #pragma unroll
        for (int k = 0; k < 6; k++) row[k] = __float2bfloat16(v[k]);
        if (half) {  // zero K-pad cols 12..15
            *(__nv_bfloat162*)(Es + el * 16 + 12) = __floats2bfloat162_rn(0.f, 0.f);
            *(__nv_bfloat162*)(Es + el * 16 + 14) = __floats2bfloat162_rn(0.f, 0.f);
        }
    }
    __syncthreads();

    float acc[4][4][4];   // [mi][ni][r]

    // ---- stage 1: GEMM1 (Es[64x16] @ W1t) -> H1, 3 n-passes ----
    {
        uint32_t a[4][4];
        const int arow = lane & 15;
        const int acol = (lane >> 4) * 8;
        #pragma unroll
        for (int mi = 0; mi < 4; mi++)
            asm volatile("ldmatrix.sync.aligned.m8n8.x4.shared.b16 {%0,%1,%2,%3}, [%4];\n"
                : "=r"(a[mi][0]), "=r"(a[mi][1]), "=r"(a[mi][2]), "=r"(a[mi][3])
                : "r"(smem_u32(Es + (arow + mi * 16) * 16 + acol)));
        #pragma unroll
        for (int p = 0; p < 3; p++) {
            const int n0 = p * 128;
            #pragma unroll
            for (int mi = 0; mi < 4; mi++)
                #pragma unroll
                for (int ni = 0; ni < 4; ni++)
                    #pragma unroll
                    for (int r = 0; r < 4; r++) acc[mi][ni][r] = 0.f;
            uint32_t b[4][2];
            const int brow = n0 + wn + (lane & 7);
            const int bcol = ((lane >> 3) & 1) * 8;
            #pragma unroll
            for (int ni = 0; ni < 4; ni++)
                asm volatile("ldmatrix.sync.aligned.m8n8.x2.shared.b16 {%0,%1}, [%2];\n"
                    : "=r"(b[ni][0]), "=r"(b[ni][1])
                    : "r"(smem_u32(W1s + (brow + ni * 8) * 16 + bcol)));
            #pragma unroll
            for (int mi = 0; mi < 4; mi++)
                #pragma unroll
                for (int ni = 0; ni < 4; ni++)
                    asm volatile("mma.sync.aligned.m16n8k16.row.col.f32.bf16.bf16.f32 "
                        "{%0,%1,%2,%3}, {%4,%5,%6,%7}, {%8,%9}, {%0,%1,%2,%3};\n"
                        : "+f"(acc[mi][ni][0]), "+f"(acc[mi][ni][1]),
                          "+f"(acc[mi][ni][2]), "+f"(acc[mi][ni][3])
                        : "r"(a[mi][0]), "r"(a[mi][1]), "r"(a[mi][2]), "r"(a[mi][3]),
                          "r"(b[ni][0]), "r"(b[ni][1]));
            #pragma unroll
            for (int mi = 0; mi < 4; mi++)
                #pragma unroll
                for (int ni = 0; ni < 4; ni++) {
                    int c0 = n0 + wn + ni * 8 + q * 2;
                    if (c0 >= 320) continue;
                    float bb0 = (c0 < 300)     ? __ldg(b1 + c0)     : 0.f;
                    float bb1 = (c0 + 1 < 300) ? __ldg(b1 + c0 + 1) : 0.f;
                    int r0 = mi * 16 + g;
                    *(__nv_bfloat162*)(H1 + r0 * SH + c0) = __floats2bfloat162_rn(
                        fmaxf(acc[mi][ni][0] + bb0, 0.f), fmaxf(acc[mi][ni][1] + bb1, 0.f));
                    *(__nv_bfloat162*)(H1 + (r0 + 8) * SH + c0) = __floats2bfloat162_rn(
                        fmaxf(acc[mi][ni][2] + bb0, 0.f), fmaxf(acc[mi][ni][3] + bb1, 0.f));
                }
        }
    }

    // ---- shared K-loop: acc = Asm[64xKP] @ Bg[n0..n0+127][KP]^T ----
    // BK=32, 3-stage cp.async ring (loads 2 chunks ahead), one barrier per chunk.
    auto kloop = [&](const __nv_bfloat16* Asm, const __nv_bfloat16* Bg) {
        #pragma unroll
        for (int mi = 0; mi < 4; mi++)
            #pragma unroll
            for (int ni = 0; ni < 4; ni++)
                #pragma unroll
                for (int r = 0; r < 4; r++) acc[mi][ni][r] = 0.f;

        auto loadB = [&](int buf, int kc) {
            // 128 rows x 32 elems (64B): 4 threads/row x 16B, 4 rounds (128 thr)
            #pragma unroll
            for (int i = 0; i < 4; i++) {
                int row = (t >> 2) + i * 32;
                const __nv_bfloat16* src = Bg + (size_t)row * KP + kc * BK + (t & 3) * 8;
                uint32_t dst = smem_u32(Bs + buf * (128 * BSTR) + row * BSTR + (t & 3) * 8);
                asm volatile("cp.async.cg.shared.global [%0], [%1], 16;\n"
                             :: "r"(dst), "l"(src));
            }
        };

        __syncthreads();               // previous users of Bs region done
        loadB(0, 0);
        asm volatile("cp.async.commit_group;\n");
        loadB(1, 1);
        asm volatile("cp.async.commit_group;\n");
        #pragma unroll 1
        for (int kc = 0; kc < NKC; kc++) {
            asm volatile("cp.async.wait_group 1;\n");  // chunk kc resident
            __syncthreads();                            // all warps past chunk kc-1
            if (kc + 2 < NKC) loadB((kc + 2) % NSTG, kc + 2);
            asm volatile("cp.async.commit_group;\n");
            const __nv_bfloat16* Bsl = Bs + (kc % NSTG) * (128 * BSTR);
            #pragma unroll
            for (int kk = 0; kk < 2; kk++) {
                uint32_t a[4][4], b[4][2];
                const int arow = lane & 15;
                const int acol = kc * BK + kk * 16 + (lane >> 4) * 8;
                #pragma unroll
                for (int mi = 0; mi < 4; mi++)
                    asm volatile("ldmatrix.sync.aligned.m8n8.x4.shared.b16 {%0,%1,%2,%3}, [%4];\n"
                        : "=r"(a[mi][0]), "=r"(a[mi][1]), "=r"(a[mi][2]), "=r"(a[mi][3])
                        : "r"(smem_u32(Asm + (arow + mi * 16) * SH + acol)));
                const int brow = wn + (lane & 7);
                const int bcol = kk * 16 + ((lane >> 3) & 1) * 8;
                #pragma unroll
                for (int ni = 0; ni < 4; ni++)
                    asm volatile("ldmatrix.sync.aligned.m8n8.x2.shared.b16 {%0,%1}, [%2];\n"
                        : "=r"(b[ni][0]), "=r"(b[ni][1])
                        : "r"(smem_u32(Bsl + (brow + ni * 8) * BSTR + bcol)));
                #pragma unroll
                for (int mi = 0; mi < 4; mi++)
                    #pragma unroll
                    for (int ni = 0; ni < 4; ni++)
                        asm volatile("mma.sync.aligned.m16n8k16.row.col.f32.bf16.bf16.f32 "
                            "{%0,%1,%2,%3}, {%4,%5,%6,%7}, {%8,%9}, {%0,%1,%2,%3};\n"
                            : "+f"(acc[mi][ni][0]), "+f"(acc[mi][ni][1]),
                              "+f"(acc[mi][ni][2]), "+f"(acc[mi][ni][3])
                            : "r"(a[mi][0]), "r"(a[mi][1]), "r"(a[mi][2]), "r"(a[mi][3]),
                              "r"(b[ni][0]), "r"(b[ni][1]));
            }
        }
    };

    // ---- stage 2: GEMM2 (H1 @ W2t) -> H2, 3 n-passes ----
    #pragma unroll 1
    for (int p = 0; p < 3; p++) {
        const int n0 = p * 128;
        kloop(H1, g_W2t + (size_t)n0 * KP);
        #pragma unroll
        for (int mi = 0; mi < 4; mi++)
            #pragma unroll
            for (int ni = 0; ni < 4; ni++) {
                int c0 = n0 + wn + ni * 8 + q * 2;
                if (c0 >= 320) continue;
                float bb0 = (c0 < 300)     ? __ldg(b2 + c0)     : 0.f;
                float bb1 = (c0 + 1 < 300) ? __ldg(b2 + c0 + 1) : 0.f;
                int r0 = mi * 16 + g;
                *(__nv_bfloat162*)(H2 + r0 * SH + c0) = __floats2bfloat162_rn(
                    fmaxf(acc[mi][ni][0] + bb0, 0.f), fmaxf(acc[mi][ni][1] + bb1, 0.f));
                *(__nv_bfloat162*)(H2 + (r0 + 8) * SH + c0) = __floats2bfloat162_rn(
                    fmaxf(acc[mi][ni][2] + bb0, 0.f), fmaxf(acc[mi][ni][3] + bb1, 0.f));
            }
    }

    // ---- stage 3: GEMM3 (H2 @ W3t), fused KL epilogue, 2 n-passes ----
    float localKL = 0.f;
    #pragma unroll 1
    for (int p = 0; p < 2; p++) {
        const int n0 = p * 128;
        kloop(H2, g_W3t + (size_t)n0 * KP);
        #pragma unroll
        for (int mi = 0; mi < 4; mi++)
            #pragma unroll
            for (int ni = 0; ni < 4; ni++) {
                int c0 = n0 + wn + ni * 8 + q * 2;
                int r0 = mBase + mi * 16 + g;
                #pragma unroll
                for (int h = 0; h < 2; h++) {
                    int r = r0 + h * 8;
                    if (r >= nEdges) continue;
                    #pragma unroll
                    for (int j = 0; j < 2; j++) {
                        int c = c0 + j;
                        if (c >= 200) continue;
                        float v = acc[mi][ni][h * 2 + j] + __ldg(b3 + c);
                        localKL += (c < 100) ? 0.5f * v * v
                                             : 0.5f * (__expf(v) - v - 1.f);
                    }
                }
            }
    }

    // ---- block reduce + atomic ----
    #pragma unroll
    for (int o = 16; o > 0; o >>= 1) localKL += __shfl_xor_sync(0xffffffffu, localKL, o);
    if (lane == 0) red[warp] = localKL;
    __syncthreads();
    if (t == 0)
        atomicAdd(&g_acc[1], (double)(red[0] + red[1] + red[2] + red[3]));
}

__global__ void k_finalize(float* out, int nNodes, int nEdges) {
    out[0] = (float)(g_acc[0] / (double)nNodes + g_acc[1] / (double)nEdges);
}

extern "C" void kernel_launch(void* const* d_in, const int* in_sizes, int n_in,
                              void* d_out, int out_size) {
    const float* x   = (const float*)d_in[0];
    const int*   ei  = (const int*)  d_in[1];
    const float* y   = (const float*)d_in[2];
    const float* tgt = (const float*)d_in[3];
    const float* W1  = (const float*)d_in[4];
    const float* b1  = (const float*)d_in[5];
    const float* W2  = (const float*)d_in[6];
    const float* b2  = (const float*)d_in[7];
    const float* W3  = (const float*)d_in[8];
    const float* b3  = (const float*)d_in[9];
    float* out = (float*)d_out;

    const int nNodes = in_sizes[0] / 6;
    const int nEdges = in_sizes[1] / 2;
    const int nY     = in_sizes[2];

    cudaFuncSetAttribute(k_fused, cudaFuncAttributeMaxDynamicSharedMemorySize, SMEM_BYTES);

    k_zero<<<1, 1>>>();
    k_base<<<128, 256>>>(y, tgt, nY);
    k_prep_w<<<(384 * KP + 255) / 256, 256>>>(W1, W2, W3);
    k_fused<<<(nEdges + BM - 1) / BM, 128, SMEM_BYTES>>>(x, ei, b1, b2, b3, nEdges);
    k_finalize<<<1, 1>>>(out, nNodes, nEdges);
}

// round 8
// speedup vs baseline: 1.6110x; 1.6110x over previous
#include <cuda_runtime.h>
#include <cuda_bf16.h>
#include <cstdint>

// ---------------- constants ----------------
#define KP    320          // padded weight K / hidden width
#define SH    328          // smem row stride (elems) for H1/H2 tiles
#define BM    64           // edges per block
#define BK    32           // k-elems per pipeline stage
#define BSTR  40           // Bs smem row stride (elems)
#define NKC   10           // k chunks per pass (320/32)
#define NSTG  2            // cp.async stages
#define NTHR  320          // 10 warps: 2m x 5n grid, warp tile 32x32

// ---------------- device scratch ----------------
__device__ __align__(16) __nv_bfloat16 g_W1t[384 * 16];   // W1^T padded [n=384][k=16]
__device__ __align__(16) __nv_bfloat16 g_W2t[384 * KP];   // W2^T padded
__device__ __align__(16) __nv_bfloat16 g_W3t[256 * KP];   // W3^T padded
__device__ double g_acc[2];                               // [0]=sum|y-t|, [1]=KL

__device__ __forceinline__ uint32_t smem_u32(const void* p) {
    return (uint32_t)__cvta_generic_to_shared(p);
}

__global__ void k_zero() { g_acc[0] = 0.0; g_acc[1] = 0.0; }

__global__ void k_base(const float* __restrict__ y, const float* __restrict__ tg, int n) {
    __shared__ float red[8];
    float local = 0.f;
    for (int i = blockIdx.x * blockDim.x + threadIdx.x; i < n; i += gridDim.x * blockDim.x)
        local += fabsf(y[i] - tg[i]);
    int lane = threadIdx.x & 31, warp = threadIdx.x >> 5;
    #pragma unroll
    for (int o = 16; o > 0; o >>= 1) local += __shfl_xor_sync(0xffffffffu, local, o);
    if (lane == 0) red[warp] = local;
    __syncthreads();
    if (threadIdx.x < 8) {
        float v = red[threadIdx.x];
        #pragma unroll
        for (int o = 4; o > 0; o >>= 1) v += __shfl_xor_sync(0xffu, v, o);
        if (threadIdx.x == 0) atomicAdd(&g_acc[0], (double)v);
    }
}

__global__ void k_prep_w(const float* __restrict__ W1,
                         const float* __restrict__ W2,
                         const float* __restrict__ W3) {
    int i = blockIdx.x * blockDim.x + threadIdx.x;
    if (i < 384 * 16) {
        int n = i / 16, k = i % 16;
        g_W1t[i] = __float2bfloat16((n < 300 && k < 12) ? W1[k * 300 + n] : 0.f);
    }
    if (i < 384 * KP) {
        int n = i / KP, k = i % KP;
        g_W2t[i] = __float2bfloat16((n < 300 && k < 300) ? W2[k * 300 + n] : 0.f);
    }
    if (i < 256 * KP) {
        int n = i / KP, k = i % KP;
        g_W3t[i] = __float2bfloat16((n < 200 && k < 300) ? W3[k * 200 + n] : 0.f);
    }
}

// ---------------- smem layout (dynamic, ~107 KB, 2 CTAs/SM) ----------------
#define OFF_H1   0
#define OFF_H2   (64 * SH)
#define OFF_BS   (2 * 64 * SH)
#define OFF_W1S  OFF_BS                       // union: W1s inside Bs region
#define OFF_ES   (OFF_BS + 384 * 16)          // union: Es after W1s
#define ELEMS_BF (2 * 64 * SH + NSTG * 160 * BSTR)
#define SMEM_BYTES (ELEMS_BF * 2 + 64)

// ---------------- generic K-loop: acc = Asm[64xKP] @ Bg[tile NROWS x KP]^T ----
// NI = n-subtiles per warp (warp n-width = NI*8); tile rows NROWS = 40*NI.
template<int NI>
__device__ __forceinline__ void kloop(const __nv_bfloat16* __restrict__ Asm,
                                      const __nv_bfloat16* __restrict__ Bg,
                                      __nv_bfloat16* Bs,
                                      float acc[2][4][4],
                                      int t, int lane, int mg, int ng) {
    constexpr int NROWS = 40 * NI;
    #pragma unroll
    for (int mi = 0; mi < 2; mi++)
        #pragma unroll
        for (int ni = 0; ni < NI; ni++)
            #pragma unroll
            for (int r = 0; r < 4; r++) acc[mi][ni][r] = 0.f;

    auto loadB = [&](int buf, int kc) {
        #pragma unroll
        for (int i = 0; i < (NROWS + 79) / 80; i++) {
            int row = (t >> 2) + i * 80;
            if (row < NROWS) {
                const __nv_bfloat16* src = Bg + (size_t)row * KP + kc * BK + (t & 3) * 8;
                uint32_t dst = smem_u32(Bs + buf * (NROWS * BSTR) + row * BSTR + (t & 3) * 8);
                asm volatile("cp.async.cg.shared.global [%0], [%1], 16;\n"
                             :: "r"(dst), "l"(src));
            }
        }
    };

    __syncthreads();               // previous users of Bs region done
    loadB(0, 0);
    asm volatile("cp.async.commit_group;\n");
    #pragma unroll 1
    for (int kc = 0; kc < NKC; kc++) {
        if (kc + 1 < NKC) loadB((kc + 1) & 1, kc + 1);
        asm volatile("cp.async.commit_group;\n");
        asm volatile("cp.async.wait_group 1;\n");   // chunk kc resident
        __syncthreads();                            // all warps past chunk kc-1
        const __nv_bfloat16* Bsl = Bs + (kc & 1) * (NROWS * BSTR);
        #pragma unroll
        for (int kk = 0; kk < 2; kk++) {
            uint32_t a[2][4], b[NI][2];
            const int arow = mg * 32 + (lane & 15);
            const int acol = kc * BK + kk * 16 + (lane >> 4) * 8;
            #pragma unroll
            for (int mi = 0; mi < 2; mi++)
                asm volatile("ldmatrix.sync.aligned.m8n8.x4.shared.b16 {%0,%1,%2,%3}, [%4];\n"
                    : "=r"(a[mi][0]), "=r"(a[mi][1]), "=r"(a[mi][2]), "=r"(a[mi][3])
                    : "r"(smem_u32(Asm + (arow + mi * 16) * SH + acol)));
            const int brow = ng * (NI * 8) + (lane & 7);
            const int bcol = kk * 16 + ((lane >> 3) & 1) * 8;
            #pragma unroll
            for (int ni = 0; ni < NI; ni++)
                asm volatile("ldmatrix.sync.aligned.m8n8.x2.shared.b16 {%0,%1}, [%2];\n"
                    : "=r"(b[ni][0]), "=r"(b[ni][1])
                    : "r"(smem_u32(Bsl + (brow + ni * 8) * BSTR + bcol)));
            #pragma unroll
            for (int mi = 0; mi < 2; mi++)
                #pragma unroll
                for (int ni = 0; ni < NI; ni++)
                    asm volatile("mma.sync.aligned.m16n8k16.row.col.f32.bf16.bf16.f32 "
                        "{%0,%1,%2,%3}, {%4,%5,%6,%7}, {%8,%9}, {%0,%1,%2,%3};\n"
                        : "+f"(acc[mi][ni][0]), "+f"(acc[mi][ni][1]),
                          "+f"(acc[mi][ni][2]), "+f"(acc[mi][ni][3])
                        : "r"(a[mi][0]), "r"(a[mi][1]), "r"(a[mi][2]), "r"(a[mi][3]),
                          "r"(b[ni][0]), "r"(b[ni][1]));
        }
    }
}

__global__ __launch_bounds__(NTHR, 2)
void k_fused(const float* __restrict__ x,
             const int*   __restrict__ ei,
             const float* __restrict__ b1,
             const float* __restrict__ b2,
             const float* __restrict__ b3,
             int nEdges) {
    extern __shared__ __align__(16) char smem_raw[];
    __nv_bfloat16* base = (__nv_bfloat16*)smem_raw;
    __nv_bfloat16* H1  = base + OFF_H1;
    __nv_bfloat16* H2  = base + OFF_H2;
    __nv_bfloat16* Bs  = base + OFF_BS;
    __nv_bfloat16* W1s = base + OFF_W1S;
    __nv_bfloat16* Es  = base + OFF_ES;
    float* red = (float*)(base + ELEMS_BF);

    const int t = threadIdx.x;
    const int lane = t & 31, warp = t >> 5;    // 10 warps
    const int mg = warp / 5;                   // 0,1  (m-group of 32 rows)
    const int ng = warp % 5;                   // 0..4 (n-group)
    const int mBase = blockIdx.x * BM;
    const int g = lane >> 2, q = lane & 3;

    // ---- stage 0: weights/edge gather into smem ----
    {
        const uint4* src = (const uint4*)g_W1t;
        uint4* dst = (uint4*)W1s;
        for (int i = t; i < 768; i += NTHR) dst[i] = src[i];
    }
    if (t < 128) {
        int el = t >> 1, half = t & 1;
        int e = mBase + el;
        __nv_bfloat16* row = Es + el * 16 + half * 6;
        float v[6] = {0.f, 0.f, 0.f, 0.f, 0.f, 0.f};
        if (e < nEdges) {
            int node = ei[half ? (size_t)nEdges + e : (size_t)e];
            const float* xp = x + (size_t)node * 6;
            float2 a0 = *(const float2*)xp;
            float2 a1 = *(const float2*)(xp + 2);
            float2 a2 = *(const float2*)(xp + 4);
            v[0] = a0.x; v[1] = a0.y; v[2] = a1.x; v[3] = a1.y; v[4] = a2.x; v[5] = a2.y;
        }
        #pragma unroll
        for (int k = 0; k < 6; k++) row[k] = __float2bfloat16(v[k]);
        if (half) {  // zero K-pad cols 12..15
            *(__nv_bfloat162*)(Es + el * 16 + 12) = __floats2bfloat162_rn(0.f, 0.f);
            *(__nv_bfloat162*)(Es + el * 16 + 14) = __floats2bfloat162_rn(0.f, 0.f);
        }
    }
    __syncthreads();

    float acc[2][4][4];

    // ---- stage 1: GEMM1 (Es[64x16] @ W1t) -> H1 ----
    // warp covers cols [ng*64, ng*64+64) in two passes of 32 (keeps regs low)
    {
        uint32_t a[2][4];
        const int arow = mg * 32 + (lane & 15);
        const int acol = (lane >> 4) * 8;
        #pragma unroll
        for (int mi = 0; mi < 2; mi++)
            asm volatile("ldmatrix.sync.aligned.m8n8.x4.shared.b16 {%0,%1,%2,%3}, [%4];\n"
                : "=r"(a[mi][0]), "=r"(a[mi][1]), "=r"(a[mi][2]), "=r"(a[mi][3])
                : "r"(smem_u32(Es + (arow + mi * 16) * 16 + acol)));
        #pragma unroll
        for (int p = 0; p < 2; p++) {
            const int n0 = ng * 64 + p * 32;
            #pragma unroll
            for (int mi = 0; mi < 2; mi++)
                #pragma unroll
                for (int ni = 0; ni < 4; ni++)
                    #pragma unroll
                    for (int r = 0; r < 4; r++) acc[mi][ni][r] = 0.f;
            uint32_t b[4][2];
            const int brow = n0 + (lane & 7);
            const int bcol = ((lane >> 3) & 1) * 8;
            #pragma unroll
            for (int ni = 0; ni < 4; ni++)
                asm volatile("ldmatrix.sync.aligned.m8n8.x2.shared.b16 {%0,%1}, [%2];\n"
                    : "=r"(b[ni][0]), "=r"(b[ni][1])
                    : "r"(smem_u32(W1s + (brow + ni * 8) * 16 + bcol)));
            #pragma unroll
            for (int mi = 0; mi < 2; mi++)
                #pragma unroll
                for (int ni = 0; ni < 4; ni++)
                    asm volatile("mma.sync.aligned.m16n8k16.row.col.f32.bf16.bf16.f32 "
                        "{%0,%1,%2,%3}, {%4,%5,%6,%7}, {%8,%9}, {%0,%1,%2,%3};\n"
                        : "+f"(acc[mi][ni][0]), "+f"(acc[mi][ni][1]),
                          "+f"(acc[mi][ni][2]), "+f"(acc[mi][ni][3])
                        : "r"(a[mi][0]), "r"(a[mi][1]), "r"(a[mi][2]), "r"(a[mi][3]),
                          "r"(b[ni][0]), "r"(b[ni][1]));
            #pragma unroll
            for (int mi = 0; mi < 2; mi++)
                #pragma unroll
                for (int ni = 0; ni < 4; ni++) {
                    int c0 = n0 + ni * 8 + q * 2;
                    float bb0 = (c0 < 300)     ? __ldg(b1 + c0)     : 0.f;
                    float bb1 = (c0 + 1 < 300) ? __ldg(b1 + c0 + 1) : 0.f;
                    int r0 = mg * 32 + mi * 16 + g;
                    *(__nv_bfloat162*)(H1 + r0 * SH + c0) = __floats2bfloat162_rn(
                        fmaxf(acc[mi][ni][0] + bb0, 0.f), fmaxf(acc[mi][ni][1] + bb1, 0.f));
                    *(__nv_bfloat162*)(H1 + (r0 + 8) * SH + c0) = __floats2bfloat162_rn(
                        fmaxf(acc[mi][ni][2] + bb0, 0.f), fmaxf(acc[mi][ni][3] + bb1, 0.f));
                }
        }
    }

    // ---- stage 2: GEMM2 (H1 @ W2t) -> H2, two BN=160 passes ----
    #pragma unroll 1
    for (int p = 0; p < 2; p++) {
        const int n0 = p * 160;
        kloop<4>(H1, g_W2t + (size_t)n0 * KP, Bs, acc, t, lane, mg, ng);
        #pragma unroll
        for (int mi = 0; mi < 2; mi++)
            #pragma unroll
            for (int ni = 0; ni < 4; ni++) {
                int c0 = n0 + ng * 32 + ni * 8 + q * 2;
                float bb0 = (c0 < 300)     ? __ldg(b2 + c0)     : 0.f;
                float bb1 = (c0 + 1 < 300) ? __ldg(b2 + c0 + 1) : 0.f;
                int r0 = mg * 32 + mi * 16 + g;
                *(__nv_bfloat162*)(H2 + r0 * SH + c0) = __floats2bfloat162_rn(
                    fmaxf(acc[mi][ni][0] + bb0, 0.f), fmaxf(acc[mi][ni][1] + bb1, 0.f));
                *(__nv_bfloat162*)(H2 + (r0 + 8) * SH + c0) = __floats2bfloat162_rn(
                    fmaxf(acc[mi][ni][2] + bb0, 0.f), fmaxf(acc[mi][ni][3] + bb1, 0.f));
            }
    }

    // ---- stage 3: GEMM3 (H2 @ W3t), fused KL, passes BN=160 then BN=40 ----
    float localKL = 0.f;
    {
        kloop<4>(H2, g_W3t, Bs, acc, t, lane, mg, ng);
        #pragma unroll
        for (int mi = 0; mi < 2; mi++)
            #pragma unroll
            for (int ni = 0; ni < 4; ni++) {
                int c0 = ng * 32 + ni * 8 + q * 2;
                int r0 = mBase + mg * 32 + mi * 16 + g;
                #pragma unroll
                for (int h = 0; h < 2; h++) {
                    if (r0 + h * 8 >= nEdges) continue;
                    #pragma unroll
                    for (int j = 0; j < 2; j++) {
                        int c = c0 + j;
                        float v = acc[mi][ni][h * 2 + j] + __ldg(b3 + c);
                        localKL += (c < 100) ? 0.5f * v * v
                                             : 0.5f * (__expf(v) - v - 1.f);
                    }
                }
            }
    }
    {
        kloop<1>(H2, g_W3t + (size_t)160 * KP, Bs, acc, t, lane, mg, ng);
        #pragma unroll
        for (int mi = 0; mi < 2; mi++) {
            int c0 = 160 + ng * 8 + q * 2;
            int r0 = mBase + mg * 32 + mi * 16 + g;
            #pragma unroll
            for (int h = 0; h < 2; h++) {
                if (r0 + h * 8 >= nEdges) continue;
                #pragma unroll
                for (int j = 0; j < 2; j++) {
                    int c = c0 + j;
                    if (c >= 200) continue;
                    float v = acc[mi][0][h * 2 + j] + __ldg(b3 + c);
                    localKL += 0.5f * (__expf(v) - v - 1.f);   // cols 160..199 = logvar
                }
            }
        }
    }

    // ---- block reduce + atomic ----
    #pragma unroll
    for (int o = 16; o > 0; o >>= 1) localKL += __shfl_xor_sync(0xffffffffu, localKL, o);
    if (lane == 0) red[warp] = localKL;
    __syncthreads();
    if (t == 0) {
        float s = 0.f;
        #pragma unroll
        for (int w = 0; w < 10; w++) s += red[w];
        atomicAdd(&g_acc[1], (double)s);
    }
}

__global__ void k_finalize(float* out, int nNodes, int nEdges) {
    out[0] = (float)(g_acc[0] / (double)nNodes + g_acc[1] / (double)nEdges);
}

extern "C" void kernel_launch(void* const* d_in, const int* in_sizes, int n_in,
                              void* d_out, int out_size) {
    const float* x   = (const float*)d_in[0];
    const int*   ei  = (const int*)  d_in[1];
    const float* y   = (const float*)d_in[2];
    const float* tgt = (const float*)d_in[3];
    const float* W1  = (const float*)d_in[4];
    const float* b1  = (const float*)d_in[5];
    const float* W2  = (const float*)d_in[6];
    const float* b2  = (const float*)d_in[7];
    const float* W3  = (const float*)d_in[8];
    const float* b3  = (const float*)d_in[9];
    float* out = (float*)d_out;

    const int nNodes = in_sizes[0] / 6;
    const int nEdges = in_sizes[1] / 2;
    const int nY     = in_sizes[2];

    cudaFuncSetAttribute(k_fused, cudaFuncAttributeMaxDynamicSharedMemorySize, SMEM_BYTES);

    k_zero<<<1, 1>>>();
    k_base<<<128, 256>>>(y, tgt, nY);
    k_prep_w<<<(384 * KP + 255) / 256, 256>>>(W1, W2, W3);
    k_fused<<<(nEdges + BM - 1) / BM, NTHR, SMEM_BYTES>>>(x, ei, b1, b2, b3, nEdges);
    k_finalize<<<1, 1>>>(out, nNodes, nEdges);
}

// round 9
// speedup vs baseline: 2.7069x; 1.6802x over previous
#include <cuda_runtime.h>
#include <cuda_bf16.h>
#include <cstdint>

// ---------------- constants ----------------
#define SH    328          // smem row stride (elems) for H1/H2 tiles (conflict-free)
#define BM    64           // edges per block
#define NTHR  320          // 10 warps: 2m x 5 item-groups

// ---------------- device scratch: weights pre-swizzled into mma fragment order ----
// fragment = 32 lanes x uint2 {b0,b1}; b0 = {W[k0][n],W[k0+1][n]}, b1 = {W[k0+8..9][n]}
// with n = base_n + lane/4, k0 = base_k + (lane%4)*2   (m16n8k16.row.col B layout)
__device__ uint2 g_W1f[40 * 32];      // (cg10, ni4)             : f = cg*4 + ni
__device__ uint2 g_W2f[800 * 32];     // (cg10, ni4, kc10, kk2)  : f = cg*80 + ni*20 + kc*2 + kk
__device__ uint2 g_W3f[500 * 32];     // (cg5,  ni5, kc10, kk2)  : f = cg*100 + ni*20 + kc*2 + kk
__device__ double g_acc[2];           // [0]=sum|y-t|, [1]=KL

__device__ __forceinline__ uint32_t smem_u32(const void* p) {
    return (uint32_t)__cvta_generic_to_shared(p);
}

__device__ __forceinline__ uint32_t pk2(const float* W, int k, int n,
                                        int K, int N, int ld) {
    float v0 = (k     < K && n < N) ? W[(size_t)k * ld + n]       : 0.f;
    float v1 = (k + 1 < K && n < N) ? W[(size_t)(k + 1) * ld + n] : 0.f;
    __nv_bfloat162 h = __floats2bfloat162_rn(v0, v1);
    return *(uint32_t*)&h;
}

__global__ void k_zero() { g_acc[0] = 0.0; g_acc[1] = 0.0; }

__global__ void k_base(const float* __restrict__ y, const float* __restrict__ tg, int n) {
    __shared__ float red[8];
    float local = 0.f;
    for (int i = blockIdx.x * blockDim.x + threadIdx.x; i < n; i += gridDim.x * blockDim.x)
        local += fabsf(y[i] - tg[i]);
    int lane = threadIdx.x & 31, warp = threadIdx.x >> 5;
    #pragma unroll
    for (int o = 16; o > 0; o >>= 1) local += __shfl_xor_sync(0xffffffffu, local, o);
    if (lane == 0) red[warp] = local;
    __syncthreads();
    if (threadIdx.x < 8) {
        float v = red[threadIdx.x];
        #pragma unroll
        for (int o = 4; o > 0; o >>= 1) v += __shfl_xor_sync(0xffu, v, o);
        if (threadIdx.x == 0) atomicAdd(&g_acc[0], (double)v);
    }
}

// ---------------- fragment prep ----------------
__global__ void k_prep(const float* __restrict__ W1,
                       const float* __restrict__ W2,
                       const float* __restrict__ W3) {
    int i = blockIdx.x * blockDim.x + threadIdx.x;
    int lane = i & 31, f = i >> 5;
    if (i < 25600) {            // W2 frags: [300][300], ld=300
        int cg = f / 80, r = f % 80;
        int ni = r / 20, kc = (r % 20) / 2, kk = r & 1;
        int n  = cg * 32 + ni * 8 + (lane >> 2);
        int k0 = kc * 32 + kk * 16 + (lane & 3) * 2;
        g_W2f[i] = make_uint2(pk2(W2, k0,     n, 300, 300, 300),
                              pk2(W2, k0 + 8, n, 300, 300, 300));
    }
    if (i < 16000) {            // W3 frags: [300][200], ld=200
        int cg = f / 100, r = f % 100;
        int ni = r / 20, kc = (r % 20) / 2, kk = r & 1;
        int n  = cg * 40 + ni * 8 + (lane >> 2);
        int k0 = kc * 32 + kk * 16 + (lane & 3) * 2;
        g_W3f[i] = make_uint2(pk2(W3, k0,     n, 300, 200, 200),
                              pk2(W3, k0 + 8, n, 300, 200, 200));
    }
    if (i < 1280) {             // W1 frags: [12][300], ld=300, K=16 single kk
        int cg = f >> 2, ni = f & 3;
        int n  = cg * 32 + ni * 8 + (lane >> 2);
        int k0 = (lane & 3) * 2;
        g_W1f[i] = make_uint2(pk2(W1, k0,     n, 12, 300, 300),
                              pk2(W1, k0 + 8, n, 12, 300, 300));
    }
}

// ---------------- smem: H1 + H2 + Es + red = ~86 KB, 2 CTAs/SM ----------------
#define ELEMS (2 * 64 * SH + 64 * 16)
#define SMEM_BYTES (ELEMS * 2 + 64)

#define MMA(acc, a, bx, by) \
    asm volatile("mma.sync.aligned.m16n8k16.row.col.f32.bf16.bf16.f32 " \
        "{%0,%1,%2,%3}, {%4,%5,%6,%7}, {%8,%9}, {%0,%1,%2,%3};\n" \
        : "+f"(acc[0]), "+f"(acc[1]), "+f"(acc[2]), "+f"(acc[3]) \
        : "r"(a[0]), "r"(a[1]), "r"(a[2]), "r"(a[3]), "r"(bx), "r"(by))

__global__ __launch_bounds__(NTHR, 2)
void k_fused(const float* __restrict__ x,
             const int*   __restrict__ ei,
             const float* __restrict__ b1,
             const float* __restrict__ b2,
             const float* __restrict__ b3,
             int nEdges) {
    extern __shared__ __align__(16) char smem_raw[];
    __nv_bfloat16* base = (__nv_bfloat16*)smem_raw;
    __nv_bfloat16* H1 = base;
    __nv_bfloat16* H2 = base + 64 * SH;
    __nv_bfloat16* Es = base + 2 * 64 * SH;
    float* red = (float*)(base + ELEMS);

    const int t = threadIdx.x;
    const int lane = t & 31, warp = t >> 5;    // 10 warps
    const int mg = warp / 5;                   // m-half (32 rows)
    const int ig = warp % 5;                   // item group
    const int mBase = blockIdx.x * BM;
    const int g = lane >> 2, q = lane & 3;

    // ---- stage 0: edge gather into Es ----
    if (t < 128) {
        int el = t >> 1, half = t & 1;
        int e = mBase + el;
        __nv_bfloat16* row = Es + el * 16 + half * 6;
        float v[6] = {0.f, 0.f, 0.f, 0.f, 0.f, 0.f};
        if (e < nEdges) {
            int node = ei[half ? (size_t)nEdges + e : (size_t)e];
            const float* xp = x + (size_t)node * 6;
            float2 a0 = *(const float2*)xp;
            float2 a1 = *(const float2*)(xp + 2);
            float2 a2 = *(const float2*)(xp + 4);
            v[0] = a0.x; v[1] = a0.y; v[2] = a1.x; v[3] = a1.y; v[4] = a2.x; v[5] = a2.y;
        }
        #pragma unroll
        for (int k = 0; k < 6; k++) row[k] = __float2bfloat16(v[k]);
        if (half) {
            *(__nv_bfloat162*)(Es + el * 16 + 12) = __floats2bfloat162_rn(0.f, 0.f);
            *(__nv_bfloat162*)(Es + el * 16 + 14) = __floats2bfloat162_rn(0.f, 0.f);
        }
    }
    __syncthreads();

    float acc[2][5][4];

    // ---- stage 1: GEMM1 (Es @ W1) -> H1 ; items cg = ig, ig+5 ----
    {
        uint32_t a[2][4];
        const int arow = mg * 32 + (lane & 15);
        const int acol = (lane >> 4) * 8;
        #pragma unroll
        for (int mi = 0; mi < 2; mi++)
            asm volatile("ldmatrix.sync.aligned.m8n8.x4.shared.b16 {%0,%1,%2,%3}, [%4];\n"
                : "=r"(a[mi][0]), "=r"(a[mi][1]), "=r"(a[mi][2]), "=r"(a[mi][3])
                : "r"(smem_u32(Es + (arow + mi * 16) * 16 + acol)));
        #pragma unroll
        for (int it = 0; it < 2; it++) {
            const int cg = ig + it * 5;
            #pragma unroll
            for (int mi = 0; mi < 2; mi++)
                #pragma unroll
                for (int ni = 0; ni < 4; ni++)
                    #pragma unroll
                    for (int r = 0; r < 4; r++) acc[mi][ni][r] = 0.f;
            const uint2* Bf = g_W1f + (size_t)cg * 4 * 32 + lane;
            #pragma unroll
            for (int ni = 0; ni < 4; ni++) {
                uint2 bv = __ldg(Bf + ni * 32);
                #pragma unroll
                for (int mi = 0; mi < 2; mi++) MMA(acc[mi][ni], a[mi], bv.x, bv.y);
            }
            #pragma unroll
            for (int mi = 0; mi < 2; mi++)
                #pragma unroll
                for (int ni = 0; ni < 4; ni++) {
                    int c0 = cg * 32 + ni * 8 + q * 2;
                    float bb0 = (c0 < 300)     ? __ldg(b1 + c0)     : 0.f;
                    float bb1 = (c0 + 1 < 300) ? __ldg(b1 + c0 + 1) : 0.f;
                    int r0 = mg * 32 + mi * 16 + g;
                    *(__nv_bfloat162*)(H1 + r0 * SH + c0) = __floats2bfloat162_rn(
                        fmaxf(acc[mi][ni][0] + bb0, 0.f), fmaxf(acc[mi][ni][1] + bb1, 0.f));
                    *(__nv_bfloat162*)(H1 + (r0 + 8) * SH + c0) = __floats2bfloat162_rn(
                        fmaxf(acc[mi][ni][2] + bb0, 0.f), fmaxf(acc[mi][ni][3] + bb1, 0.f));
                }
        }
    }
    __syncthreads();   // H1 published

    // ---- stage 2: GEMM2 (H1 @ W2) -> H2 ; items cg = ig, ig+5 ; NO inner barriers ----
    const uint32_t aBase1 = smem_u32(H1 + (mg * 32 + (lane & 15)) * SH) + ((lane >> 4) * 8) * 2;
    #pragma unroll 1
    for (int it = 0; it < 2; it++) {
        const int cg = ig + it * 5;
        #pragma unroll
        for (int mi = 0; mi < 2; mi++)
            #pragma unroll
            for (int ni = 0; ni < 4; ni++)
                #pragma unroll
                for (int r = 0; r < 4; r++) acc[mi][ni][r] = 0.f;
        const uint2* Bf = g_W2f + (size_t)cg * 80 * 32 + lane;
        #pragma unroll
        for (int kc = 0; kc < 10; kc++) {
            #pragma unroll
            for (int kk = 0; kk < 2; kk++) {
                uint32_t a[2][4];
                const uint32_t ac = aBase1 + (kc * 32 + kk * 16) * 2;
                #pragma unroll
                for (int mi = 0; mi < 2; mi++)
                    asm volatile("ldmatrix.sync.aligned.m8n8.x4.shared.b16 {%0,%1,%2,%3}, [%4];\n"
                        : "=r"(a[mi][0]), "=r"(a[mi][1]), "=r"(a[mi][2]), "=r"(a[mi][3])
                        : "r"(ac + mi * 16 * SH * 2));
                uint2 bv[4];
                #pragma unroll
                for (int ni = 0; ni < 4; ni++)
                    bv[ni] = __ldg(Bf + (ni * 20 + kc * 2 + kk) * 32);
                #pragma unroll
                for (int mi = 0; mi < 2; mi++)
                    #pragma unroll
                    for (int ni = 0; ni < 4; ni++)
                        MMA(acc[mi][ni], a[mi], bv[ni].x, bv[ni].y);
            }
        }
        #pragma unroll
        for (int mi = 0; mi < 2; mi++)
            #pragma unroll
            for (int ni = 0; ni < 4; ni++) {
                int c0 = cg * 32 + ni * 8 + q * 2;
                float bb0 = (c0 < 300)     ? __ldg(b2 + c0)     : 0.f;
                float bb1 = (c0 + 1 < 300) ? __ldg(b2 + c0 + 1) : 0.f;
                int r0 = mg * 32 + mi * 16 + g;
                *(__nv_bfloat162*)(H2 + r0 * SH + c0) = __floats2bfloat162_rn(
                    fmaxf(acc[mi][ni][0] + bb0, 0.f), fmaxf(acc[mi][ni][1] + bb1, 0.f));
                *(__nv_bfloat162*)(H2 + (r0 + 8) * SH + c0) = __floats2bfloat162_rn(
                    fmaxf(acc[mi][ni][2] + bb0, 0.f), fmaxf(acc[mi][ni][3] + bb1, 0.f));
            }
    }
    __syncthreads();   // H2 published

    // ---- stage 3: GEMM3 (H2 @ W3), NI=5, cols cg*40..+40, fused KL ----
    float localKL = 0.f;
    {
        const int cg = ig;
        #pragma unroll
        for (int mi = 0; mi < 2; mi++)
            #pragma unroll
            for (int ni = 0; ni < 5; ni++)
                #pragma unroll
                for (int r = 0; r < 4; r++) acc[mi][ni][r] = 0.f;
        const uint32_t aBase2 = smem_u32(H2 + (mg * 32 + (lane & 15)) * SH) + ((lane >> 4) * 8) * 2;
        const uint2* Bf = g_W3f + (size_t)cg * 100 * 32 + lane;
        #pragma unroll
        for (int kc = 0; kc < 10; kc++) {
            #pragma unroll
            for (int kk = 0; kk < 2; kk++) {
                uint32_t a[2][4];
                const uint32_t ac = aBase2 + (kc * 32 + kk * 16) * 2;
                #pragma unroll
                for (int mi = 0; mi < 2; mi++)
                    asm volatile("ldmatrix.sync.aligned.m8n8.x4.shared.b16 {%0,%1,%2,%3}, [%4];\n"
                        : "=r"(a[mi][0]), "=r"(a[mi][1]), "=r"(a[mi][2]), "=r"(a[mi][3])
                        : "r"(ac + mi * 16 * SH * 2));
                uint2 bv[5];
                #pragma unroll
                for (int ni = 0; ni < 5; ni++)
                    bv[ni] = __ldg(Bf + (ni * 20 + kc * 2 + kk) * 32);
                #pragma unroll
                for (int mi = 0; mi < 2; mi++)
                    #pragma unroll
                    for (int ni = 0; ni < 5; ni++)
                        MMA(acc[mi][ni], a[mi], bv[ni].x, bv[ni].y);
            }
        }
        #pragma unroll
        for (int mi = 0; mi < 2; mi++)
            #pragma unroll
            for (int ni = 0; ni < 5; ni++) {
                int c0 = cg * 40 + ni * 8 + q * 2;       // 0..199, no col guard needed
                int r0 = mBase + mg * 32 + mi * 16 + g;
                float bb0 = __ldg(b3 + c0), bb1 = __ldg(b3 + c0 + 1);
                #pragma unroll
                for (int h = 0; h < 2; h++) {
                    if (r0 + h * 8 >= nEdges) continue;
                    float v0 = acc[mi][ni][h * 2]     + bb0;
                    float v1 = acc[mi][ni][h * 2 + 1] + bb1;
                    localKL += (c0 < 100) ? 0.5f * (v0 * v0 + v1 * v1)
                                          : 0.5f * ((__expf(v0) - v0 - 1.f)
                                                  + (__expf(v1) - v1 - 1.f));
                }
            }
    }

    // ---- block reduce + atomic ----
    #pragma unroll
    for (int o = 16; o > 0; o >>= 1) localKL += __shfl_xor_sync(0xffffffffu, localKL, o);
    if (lane == 0) red[warp] = localKL;
    __syncthreads();
    if (t == 0) {
        float s = 0.f;
        #pragma unroll
        for (int w = 0; w < 10; w++) s += red[w];
        atomicAdd(&g_acc[1], (double)s);
    }
}

__global__ void k_finalize(float* out, int nNodes, int nEdges) {
    out[0] = (float)(g_acc[0] / (double)nNodes + g_acc[1] / (double)nEdges);
}

extern "C" void kernel_launch(void* const* d_in, const int* in_sizes, int n_in,
                              void* d_out, int out_size) {
    const float* x   = (const float*)d_in[0];
    const int*   ei  = (const int*)  d_in[1];
    const float* y   = (const float*)d_in[2];
    const float* tgt = (const float*)d_in[3];
    const float* W1  = (const float*)d_in[4];
    const float* b1  = (const float*)d_in[5];
    const float* W2  = (const float*)d_in[6];
    const float* b2  = (const float*)d_in[7];
    const float* W3  = (const float*)d_in[8];
    const float* b3  = (const float*)d_in[9];
    float* out = (float*)d_out;

    const int nNodes = in_sizes[0] / 6;
    const int nEdges = in_sizes[1] / 2;
    const int nY     = in_sizes[2];

    cudaFuncSetAttribute(k_fused, cudaFuncAttributeMaxDynamicSharedMemorySize, SMEM_BYTES);

    k_zero<<<1, 1>>>();
    k_base<<<128, 256>>>(y, tgt, nY);
    k_prep<<<(25600 + 255) / 256, 256>>>(W1, W2, W3);
    k_fused<<<(nEdges + BM - 1) / BM, NTHR, SMEM_BYTES>>>(x, ei, b1, b2, b3, nEdges);
    k_finalize<<<1, 1>>>(out, nNodes, nEdges);
}

// round 10
// speedup vs baseline: 2.7185x; 1.0043x over previous
#include <cuda_runtime.h>
#include <cuda_bf16.h>
#include <cstdint>

// ---------------- constants ----------------
#define SH    328          // smem row stride (elems) for H1/H2 tiles (conflict-free)
#define BM    64           // edges per block
#define NTHR  320          // 10 warps

// ---------------- device scratch: weights pre-swizzled into mma fragment order ----
// fragment = 32 lanes x uint2 {b0,b1}; b0 = {W[k0][n],W[k0+1][n]}, b1 = {W[k0+8..9][n]}
// with n = base_n + lane/4, k0 = base_k + (lane%4)*2   (m16n8k16.row.col B layout)
__device__ uint2 g_W1f[40 * 32];      // (cg10, ni4)             : f = cg*4 + ni
__device__ uint2 g_W2f[800 * 32];     // (cg10, ni4, kc10, kk2)  : f = cg*80 + ni*20 + kc*2 + kk
__device__ uint2 g_W3f[500 * 32];     // (cg5,  ni5, kc10, kk2)  : f = cg*100 + ni*20 + kc*2 + kk
__device__ double g_acc[2];           // [0]=sum|y-t|, [1]=KL

__device__ __forceinline__ uint32_t smem_u32(const void* p) {
    return (uint32_t)__cvta_generic_to_shared(p);
}

__device__ __forceinline__ uint32_t pk2(const float* W, int k, int n,
                                        int K, int N, int ld) {
    float v0 = (k     < K && n < N) ? W[(size_t)k * ld + n]       : 0.f;
    float v1 = (k + 1 < K && n < N) ? W[(size_t)(k + 1) * ld + n] : 0.f;
    __nv_bfloat162 h = __floats2bfloat162_rn(v0, v1);
    return *(uint32_t*)&h;
}

__global__ void k_zero() { g_acc[0] = 0.0; g_acc[1] = 0.0; }

__global__ void k_base(const float* __restrict__ y, const float* __restrict__ tg, int n) {
    __shared__ float red[8];
    float local = 0.f;
    for (int i = blockIdx.x * blockDim.x + threadIdx.x; i < n; i += gridDim.x * blockDim.x)
        local += fabsf(y[i] - tg[i]);
    int lane = threadIdx.x & 31, warp = threadIdx.x >> 5;
    #pragma unroll
    for (int o = 16; o > 0; o >>= 1) local += __shfl_xor_sync(0xffffffffu, local, o);
    if (lane == 0) red[warp] = local;
    __syncthreads();
    if (threadIdx.x < 8) {
        float v = red[threadIdx.x];
        #pragma unroll
        for (int o = 4; o > 0; o >>= 1) v += __shfl_xor_sync(0xffu, v, o);
        if (threadIdx.x == 0) atomicAdd(&g_acc[0], (double)v);
    }
}

// ---------------- fragment prep ----------------
__global__ void k_prep(const float* __restrict__ W1,
                       const float* __restrict__ W2,
                       const float* __restrict__ W3) {
    int i = blockIdx.x * blockDim.x + threadIdx.x;
    int lane = i & 31, f = i >> 5;
    if (i < 25600) {            // W2 frags: [300][300], ld=300
        int cg = f / 80, r = f % 80;
        int ni = r / 20, kc = (r % 20) / 2, kk = r & 1;
        int n  = cg * 32 + ni * 8 + (lane >> 2);
        int k0 = kc * 32 + kk * 16 + (lane & 3) * 2;
        g_W2f[i] = make_uint2(pk2(W2, k0,     n, 300, 300, 300),
                              pk2(W2, k0 + 8, n, 300, 300, 300));
    }
    if (i < 16000) {            // W3 frags: [300][200], ld=200
        int cg = f / 100, r = f % 100;
        int ni = r / 20, kc = (r % 20) / 2, kk = r & 1;
        int n  = cg * 40 + ni * 8 + (lane >> 2);
        int k0 = kc * 32 + kk * 16 + (lane & 3) * 2;
        g_W3f[i] = make_uint2(pk2(W3, k0,     n, 300, 200, 200),
                              pk2(W3, k0 + 8, n, 300, 200, 200));
    }
    if (i < 1280) {             // W1 frags: [12][300], ld=300, K=16 single kk
        int cg = f >> 2, ni = f & 3;
        int n  = cg * 32 + ni * 8 + (lane >> 2);
        int k0 = (lane & 3) * 2;
        g_W1f[i] = make_uint2(pk2(W1, k0,     n, 12, 300, 300),
                              pk2(W1, k0 + 8, n, 12, 300, 300));
    }
}

// ---------------- smem: H1 + H2 + Es + red = ~86 KB, 2 CTAs/SM ----------------
#define ELEMS (2 * 64 * SH + 64 * 16)
#define SMEM_BYTES (ELEMS * 2 + 64)

#define MMA(acc, a, bx, by) \
    asm volatile("mma.sync.aligned.m16n8k16.row.col.f32.bf16.bf16.f32 " \
        "{%0,%1,%2,%3}, {%4,%5,%6,%7}, {%8,%9}, {%0,%1,%2,%3};\n" \
        : "+f"(acc[0]), "+f"(acc[1]), "+f"(acc[2]), "+f"(acc[3]) \
        : "r"(a[0]), "r"(a[1]), "r"(a[2]), "r"(a[3]), "r"(bx), "r"(by))

__global__ __launch_bounds__(NTHR, 2)
void k_fused(const float* __restrict__ x,
             const int*   __restrict__ ei,
             const float* __restrict__ b1,
             const float* __restrict__ b2,
             const float* __restrict__ b3,
             int nEdges) {
    extern __shared__ __align__(16) char smem_raw[];
    __nv_bfloat16* base = (__nv_bfloat16*)smem_raw;
    __nv_bfloat16* H1 = base;
    __nv_bfloat16* H2 = base + 64 * SH;
    __nv_bfloat16* Es = base + 2 * 64 * SH;
    float* red = (float*)(base + ELEMS);

    const int t = threadIdx.x;
    const int lane = t & 31, warp = t >> 5;    // 10 warps
    const int mg = warp / 5;                   // m-half (stage 1/3)
    const int ig = warp % 5;                   // item group (stage 1/3)
    const int mBase = blockIdx.x * BM;
    const int g = lane >> 2, q = lane & 3;

    // ---- stage 0: edge gather into Es ----
    if (t < 128) {
        int el = t >> 1, half = t & 1;
        int e = mBase + el;
        __nv_bfloat16* row = Es + el * 16 + half * 6;
        float v[6] = {0.f, 0.f, 0.f, 0.f, 0.f, 0.f};
        if (e < nEdges) {
            int node = ei[half ? (size_t)nEdges + e : (size_t)e];
            const float* xp = x + (size_t)node * 6;
            float2 a0 = *(const float2*)xp;
            float2 a1 = *(const float2*)(xp + 2);
            float2 a2 = *(const float2*)(xp + 4);
            v[0] = a0.x; v[1] = a0.y; v[2] = a1.x; v[3] = a1.y; v[4] = a2.x; v[5] = a2.y;
        }
        #pragma unroll
        for (int k = 0; k < 6; k++) row[k] = __float2bfloat16(v[k]);
        if (half) {
            *(__nv_bfloat162*)(Es + el * 16 + 12) = __floats2bfloat162_rn(0.f, 0.f);
            *(__nv_bfloat162*)(Es + el * 16 + 14) = __floats2bfloat162_rn(0.f, 0.f);
        }
    }
    __syncthreads();

    // ---- stage 1: GEMM1 (Es @ W1) -> H1 ; 2mg x 5ig, items cg = ig, ig+5 ----
    {
        float acc[2][4][4];
        uint32_t a[2][4];
        const int arow = mg * 32 + (lane & 15);
        const int acol = (lane >> 4) * 8;
        #pragma unroll
        for (int mi = 0; mi < 2; mi++)
            asm volatile("ldmatrix.sync.aligned.m8n8.x4.shared.b16 {%0,%1,%2,%3}, [%4];\n"
                : "=r"(a[mi][0]), "=r"(a[mi][1]), "=r"(a[mi][2]), "=r"(a[mi][3])
                : "r"(smem_u32(Es + (arow + mi * 16) * 16 + acol)));
        #pragma unroll
        for (int it = 0; it < 2; it++) {
            const int cg = ig + it * 5;
            #pragma unroll
            for (int mi = 0; mi < 2; mi++)
                #pragma unroll
                for (int ni = 0; ni < 4; ni++)
                    #pragma unroll
                    for (int r = 0; r < 4; r++) acc[mi][ni][r] = 0.f;
            const uint2* Bf = g_W1f + (size_t)cg * 4 * 32 + lane;
            #pragma unroll
            for (int ni = 0; ni < 4; ni++) {
                uint2 bv = __ldg(Bf + ni * 32);
                #pragma unroll
                for (int mi = 0; mi < 2; mi++) MMA(acc[mi][ni], a[mi], bv.x, bv.y);
            }
            #pragma unroll
            for (int mi = 0; mi < 2; mi++)
                #pragma unroll
                for (int ni = 0; ni < 4; ni++) {
                    int c0 = cg * 32 + ni * 8 + q * 2;
                    float bb0 = (c0 < 300)     ? __ldg(b1 + c0)     : 0.f;
                    float bb1 = (c0 + 1 < 300) ? __ldg(b1 + c0 + 1) : 0.f;
                    int r0 = mg * 32 + mi * 16 + g;
                    *(__nv_bfloat162*)(H1 + r0 * SH + c0) = __floats2bfloat162_rn(
                        fmaxf(acc[mi][ni][0] + bb0, 0.f), fmaxf(acc[mi][ni][1] + bb1, 0.f));
                    *(__nv_bfloat162*)(H1 + (r0 + 8) * SH + c0) = __floats2bfloat162_rn(
                        fmaxf(acc[mi][ni][2] + bb0, 0.f), fmaxf(acc[mi][ni][3] + bb1, 0.f));
                }
        }
    }
    __syncthreads();   // H1 published

    // ---- stage 2: GEMM2 (H1 @ W2) -> H2 ; ONE item per warp, mi=4, NI=4 ----
    // warp = item cg (0..9): cols cg*32..+32, rows 0..63. 1.5 L1-wf per MMA tile.
    {
        float acc[4][4][4];
        const int cg = warp;
        #pragma unroll
        for (int mi = 0; mi < 4; mi++)
            #pragma unroll
            for (int ni = 0; ni < 4; ni++)
                #pragma unroll
                for (int r = 0; r < 4; r++) acc[mi][ni][r] = 0.f;
        const uint32_t aBase1 = smem_u32(H1 + (lane & 15) * SH) + ((lane >> 4) * 8) * 2;
        const uint2* Bf = g_W2f + (size_t)cg * 80 * 32 + lane;
        #pragma unroll
        for (int kc = 0; kc < 10; kc++) {
            #pragma unroll
            for (int kk = 0; kk < 2; kk++) {
                uint32_t a[4][4];
                const uint32_t ac = aBase1 + (kc * 32 + kk * 16) * 2;
                #pragma unroll
                for (int mi = 0; mi < 4; mi++)
                    asm volatile("ldmatrix.sync.aligned.m8n8.x4.shared.b16 {%0,%1,%2,%3}, [%4];\n"
                        : "=r"(a[mi][0]), "=r"(a[mi][1]), "=r"(a[mi][2]), "=r"(a[mi][3])
                        : "r"(ac + mi * 16 * SH * 2));
                uint2 bv[4];
                #pragma unroll
                for (int ni = 0; ni < 4; ni++)
                    bv[ni] = __ldg(Bf + (ni * 20 + kc * 2 + kk) * 32);
                #pragma unroll
                for (int mi = 0; mi < 4; mi++)
                    #pragma unroll
                    for (int ni = 0; ni < 4; ni++)
                        MMA(acc[mi][ni], a[mi], bv[ni].x, bv[ni].y);
            }
        }
        #pragma unroll
        for (int mi = 0; mi < 4; mi++)
            #pragma unroll
            for (int ni = 0; ni < 4; ni++) {
                int c0 = cg * 32 + ni * 8 + q * 2;
                float bb0 = (c0 < 300)     ? __ldg(b2 + c0)     : 0.f;
                float bb1 = (c0 + 1 < 300) ? __ldg(b2 + c0 + 1) : 0.f;
                int r0 = mi * 16 + g;
                *(__nv_bfloat162*)(H2 + r0 * SH + c0) = __floats2bfloat162_rn(
                    fmaxf(acc[mi][ni][0] + bb0, 0.f), fmaxf(acc[mi][ni][1] + bb1, 0.f));
                *(__nv_bfloat162*)(H2 + (r0 + 8) * SH + c0) = __floats2bfloat162_rn(
                    fmaxf(acc[mi][ni][2] + bb0, 0.f), fmaxf(acc[mi][ni][3] + bb1, 0.f));
            }
    }
    __syncthreads();   // H2 published

    // ---- stage 3: GEMM3 (H2 @ W3), 2mg x 5ig, NI=5, cols ig*40..+40, fused KL ----
    float localKL = 0.f;
    {
        float acc[2][5][4];
        const int cg = ig;
        #pragma unroll
        for (int mi = 0; mi < 2; mi++)
            #pragma unroll
            for (int ni = 0; ni < 5; ni++)
                #pragma unroll
                for (int r = 0; r < 4; r++) acc[mi][ni][r] = 0.f;
        const uint32_t aBase2 = smem_u32(H2 + (mg * 32 + (lane & 15)) * SH) + ((lane >> 4) * 8) * 2;
        const uint2* Bf = g_W3f + (size_t)cg * 100 * 32 + lane;
        #pragma unroll
        for (int kc = 0; kc < 10; kc++) {
            #pragma unroll
            for (int kk = 0; kk < 2; kk++) {
                uint32_t a[2][4];
                const uint32_t ac = aBase2 + (kc * 32 + kk * 16) * 2;
                #pragma unroll
                for (int mi = 0; mi < 2; mi++)
                    asm volatile("ldmatrix.sync.aligned.m8n8.x4.shared.b16 {%0,%1,%2,%3}, [%4];\n"
                        : "=r"(a[mi][0]), "=r"(a[mi][1]), "=r"(a[mi][2]), "=r"(a[mi][3])
                        : "r"(ac + mi * 16 * SH * 2));
                uint2 bv[5];
                #pragma unroll
                for (int ni = 0; ni < 5; ni++)
                    bv[ni] = __ldg(Bf + (ni * 20 + kc * 2 + kk) * 32);
                #pragma unroll
                for (int mi = 0; mi < 2; mi++)
                    #pragma unroll
                    for (int ni = 0; ni < 5; ni++)
                        MMA(acc[mi][ni], a[mi], bv[ni].x, bv[ni].y);
            }
        }
        #pragma unroll
        for (int mi = 0; mi < 2; mi++)
            #pragma unroll
            for (int ni = 0; ni < 5; ni++) {
                int c0 = cg * 40 + ni * 8 + q * 2;       // 0..199, no col guard needed
                int r0 = mBase + mg * 32 + mi * 16 + g;
                float bb0 = __ldg(b3 + c0), bb1 = __ldg(b3 + c0 + 1);
                #pragma unroll
                for (int h = 0; h < 2; h++) {
                    if (r0 + h * 8 >= nEdges) continue;
                    float v0 = acc[mi][ni][h * 2]     + bb0;
                    float v1 = acc[mi][ni][h * 2 + 1] + bb1;
                    localKL += (c0 < 100) ? 0.5f * (v0 * v0 + v1 * v1)
                                          : 0.5f * ((__expf(v0) - v0 - 1.f)
                                                  + (__expf(v1) - v1 - 1.f));
                }
            }
    }

    // ---- block reduce + atomic ----
    #pragma unroll
    for (int o = 16; o > 0; o >>= 1) localKL += __shfl_xor_sync(0xffffffffu, localKL, o);
    if (lane == 0) red[warp] = localKL;
    __syncthreads();
    if (t == 0) {
        float s = 0.f;
        #pragma unroll
        for (int w = 0; w < 10; w++) s += red[w];
        atomicAdd(&g_acc[1], (double)s);
    }
}

__global__ void k_finalize(float* out, int nNodes, int nEdges) {
    out[0] = (float)(g_acc[0] / (double)nNodes + g_acc[1] / (double)nEdges);
}

extern "C" void kernel_launch(void* const* d_in, const int* in_sizes, int n_in,
                              void* d_out, int out_size) {
    const float* x   = (const float*)d_in[0];
    const int*   ei  = (const int*)  d_in[1];
    const float* y   = (const float*)d_in[2];
    const float* tgt = (const float*)d_in[3];
    const float* W1  = (const float*)d_in[4];
    const float* b1  = (const float*)d_in[5];
    const float* W2  = (const float*)d_in[6];
    const float* b2  = (const float*)d_in[7];
    const float* W3  = (const float*)d_in[8];
    const float* b3  = (const float*)d_in[9];
    float* out = (float*)d_out;

    const int nNodes = in_sizes[0] / 6;
    const int nEdges = in_sizes[1] / 2;
    const int nY     = in_sizes[2];

    cudaFuncSetAttribute(k_fused, cudaFuncAttributeMaxDynamicSharedMemorySize, SMEM_BYTES);

    k_zero<<<1, 1>>>();
    k_base<<<128, 256>>>(y, tgt, nY);
    k_prep<<<(25600 + 255) / 256, 256>>>(W1, W2, W3);
    k_fused<<<(nEdges + BM - 1) / BM, NTHR, SMEM_BYTES>>>(x, ei, b1, b2, b3, nEdges);
    k_finalize<<<1, 1>>>(out, nNodes, nEdges);
}

// round 11
// speedup vs baseline: 2.8354x; 1.0430x over previous
#include <cuda_runtime.h>
#include <cuda_bf16.h>
#include <cstdint>

// ---------------- constants ----------------
#define SH    328          // smem row stride (elems) for H1/H2 tiles (conflict-free)
#define BM    64           // edges per block
#define NTHR  320          // 10 warps
// K padded to 304 = 19 k-steps of 16 (real K = 300)

// ---------------- device scratch: weights pre-swizzled into mma fragment order ----
// uint2 fragment = 32 lanes x {b0,b1}: b0={W[k0][n],W[k0+1][n]}, b1={W[k0+8..9][n]}
// n = base_n + lane/4, k0 = base_k + (lane%4)*2   (m16n8k16.row.col B layout)
// uint4 pair = fragments for k-steps (2*ksp, 2*ksp+1): {x,y}=even step, {z,w}=odd step
__device__ uint2 g_W1f[40 * 32];       // (cg10, ni4): f = cg*4 + ni
__device__ uint4 g_W2q[400 * 32];      // (cg10, ni4, ksp10): f = cg*40 + ni*10 + ksp
__device__ uint4 g_W3q[250 * 32];      // (cg5,  ni5, ksp10): f = cg*50 + ni*10 + ksp
__device__ double g_acc[2];            // [0]=sum|y-t|, [1]=KL

__device__ __forceinline__ uint32_t smem_u32(const void* p) {
    return (uint32_t)__cvta_generic_to_shared(p);
}

__device__ __forceinline__ uint32_t pk2(const float* W, int k, int n,
                                        int K, int N, int ld) {
    float v0 = (k     < K && n < N) ? W[(size_t)k * ld + n]       : 0.f;
    float v1 = (k + 1 < K && n < N) ? W[(size_t)(k + 1) * ld + n] : 0.f;
    __nv_bfloat162 h = __floats2bfloat162_rn(v0, v1);
    return *(uint32_t*)&h;
}

__global__ void k_zero() { g_acc[0] = 0.0; g_acc[1] = 0.0; }

__global__ void k_base(const float* __restrict__ y, const float* __restrict__ tg, int n) {
    __shared__ float red[8];
    float local = 0.f;
    for (int i = blockIdx.x * blockDim.x + threadIdx.x; i < n; i += gridDim.x * blockDim.x)
        local += fabsf(y[i] - tg[i]);
    int lane = threadIdx.x & 31, warp = threadIdx.x >> 5;
    #pragma unroll
    for (int o = 16; o > 0; o >>= 1) local += __shfl_xor_sync(0xffffffffu, local, o);
    if (lane == 0) red[warp] = local;
    __syncthreads();
    if (threadIdx.x < 8) {
        float v = red[threadIdx.x];
        #pragma unroll
        for (int o = 4; o > 0; o >>= 1) v += __shfl_xor_sync(0xffu, v, o);
        if (threadIdx.x == 0) atomicAdd(&g_acc[0], (double)v);
    }
}

// ---------------- fragment prep ----------------
__global__ void k_prep(const float* __restrict__ W1,
                       const float* __restrict__ W2,
                       const float* __restrict__ W3) {
    int i = blockIdx.x * blockDim.x + threadIdx.x;
    int lane = i & 31, f = i >> 5;
    if (i < 12800) {            // W2q: [300][300], ld=300
        int cg = f / 40, r = f % 40;
        int ni = r / 10, ksp = r % 10;
        int n  = cg * 32 + ni * 8 + (lane >> 2);
        int k0 = ksp * 32 + (lane & 3) * 2;      // even step base = 2*ksp*16
        g_W2q[i] = make_uint4(pk2(W2, k0,      n, 300, 300, 300),
                              pk2(W2, k0 + 8,  n, 300, 300, 300),
                              pk2(W2, k0 + 16, n, 300, 300, 300),
                              pk2(W2, k0 + 24, n, 300, 300, 300));
    }
    if (i < 8000) {             // W3q: [300][200], ld=200
        int cg = f / 50, r = f % 50;
        int ni = r / 10, ksp = r % 10;
        int n  = cg * 40 + ni * 8 + (lane >> 2);
        int k0 = ksp * 32 + (lane & 3) * 2;
        g_W3q[i] = make_uint4(pk2(W3, k0,      n, 300, 200, 200),
                              pk2(W3, k0 + 8,  n, 300, 200, 200),
                              pk2(W3, k0 + 16, n, 300, 200, 200),
                              pk2(W3, k0 + 24, n, 300, 200, 200));
    }
    if (i < 1280) {             // W1: [12][300], ld=300, K=16 single step
        int cg = f >> 2, ni = f & 3;
        int n  = cg * 32 + ni * 8 + (lane >> 2);
        int k0 = (lane & 3) * 2;
        g_W1f[i] = make_uint2(pk2(W1, k0,     n, 12, 300, 300),
                              pk2(W1, k0 + 8, n, 12, 300, 300));
    }
}

// ---------------- smem: H1 + H2 + Es + red = ~86 KB, 2 CTAs/SM ----------------
#define ELEMS (2 * 64 * SH + 64 * 16)
#define SMEM_BYTES (ELEMS * 2 + 64)

#define MMA(acc, a, bx, by) \
    asm volatile("mma.sync.aligned.m16n8k16.row.col.f32.bf16.bf16.f32 " \
        "{%0,%1,%2,%3}, {%4,%5,%6,%7}, {%8,%9}, {%0,%1,%2,%3};\n" \
        : "+f"(acc[0]), "+f"(acc[1]), "+f"(acc[2]), "+f"(acc[3]) \
        : "r"(a[0]), "r"(a[1]), "r"(a[2]), "r"(a[3]), "r"(bx), "r"(by))

__global__ __launch_bounds__(NTHR, 2)
void k_fused(const float* __restrict__ x,
             const int*   __restrict__ ei,
             const float* __restrict__ b1,
             const float* __restrict__ b2,
             const float* __restrict__ b3,
             int nEdges) {
    extern __shared__ __align__(16) char smem_raw[];
    __nv_bfloat16* base = (__nv_bfloat16*)smem_raw;
    __nv_bfloat16* H1 = base;
    __nv_bfloat16* H2 = base + 64 * SH;
    __nv_bfloat16* Es = base + 2 * 64 * SH;
    float* red = (float*)(base + ELEMS);

    const int t = threadIdx.x;
    const int lane = t & 31, warp = t >> 5;    // 10 warps
    const int mg = warp / 5;                   // m-half (stage 1/3)
    const int ig = warp % 5;                   // item group (stage 1/3)
    const int mBase = blockIdx.x * BM;
    const int g = lane >> 2, q = lane & 3;

    // ---- stage 0: edge gather into Es ----
    if (t < 128) {
        int el = t >> 1, half = t & 1;
        int e = mBase + el;
        __nv_bfloat16* row = Es + el * 16 + half * 6;
        float v[6] = {0.f, 0.f, 0.f, 0.f, 0.f, 0.f};
        if (e < nEdges) {
            int node = ei[half ? (size_t)nEdges + e : (size_t)e];
            const float* xp = x + (size_t)node * 6;
            float2 a0 = *(const float2*)xp;
            float2 a1 = *(const float2*)(xp + 2);
            float2 a2 = *(const float2*)(xp + 4);
            v[0] = a0.x; v[1] = a0.y; v[2] = a1.x; v[3] = a1.y; v[4] = a2.x; v[5] = a2.y;
        }
        #pragma unroll
        for (int k = 0; k < 6; k++) row[k] = __float2bfloat16(v[k]);
        if (half) {
            *(__nv_bfloat162*)(Es + el * 16 + 12) = __floats2bfloat162_rn(0.f, 0.f);
            *(__nv_bfloat162*)(Es + el * 16 + 14) = __floats2bfloat162_rn(0.f, 0.f);
        }
    }
    __syncthreads();

    // ---- stage 1: GEMM1 (Es @ W1) -> H1 ; 2mg x 5ig, items cg = ig, ig+5 ----
    {
        float acc[2][4][4];
        uint32_t a[2][4];
        const int arow = mg * 32 + (lane & 15);
        const int acol = (lane >> 4) * 8;
        #pragma unroll
        for (int mi = 0; mi < 2; mi++)
            asm volatile("ldmatrix.sync.aligned.m8n8.x4.shared.b16 {%0,%1,%2,%3}, [%4];\n"
                : "=r"(a[mi][0]), "=r"(a[mi][1]), "=r"(a[mi][2]), "=r"(a[mi][3])
                : "r"(smem_u32(Es + (arow + mi * 16) * 16 + acol)));
        #pragma unroll
        for (int it = 0; it < 2; it++) {
            const int cg = ig + it * 5;
            #pragma unroll
            for (int mi = 0; mi < 2; mi++)
                #pragma unroll
                for (int ni = 0; ni < 4; ni++)
                    #pragma unroll
                    for (int r = 0; r < 4; r++) acc[mi][ni][r] = 0.f;
            const uint2* Bf = g_W1f + (size_t)cg * 4 * 32 + lane;
            #pragma unroll
            for (int ni = 0; ni < 4; ni++) {
                uint2 bv = __ldg(Bf + ni * 32);
                #pragma unroll
                for (int mi = 0; mi < 2; mi++) MMA(acc[mi][ni], a[mi], bv.x, bv.y);
            }
            #pragma unroll
            for (int mi = 0; mi < 2; mi++)
                #pragma unroll
                for (int ni = 0; ni < 4; ni++) {
                    int c0 = cg * 32 + ni * 8 + q * 2;
                    float bb0 = (c0 < 300)     ? __ldg(b1 + c0)     : 0.f;
                    float bb1 = (c0 + 1 < 300) ? __ldg(b1 + c0 + 1) : 0.f;
                    int r0 = mg * 32 + mi * 16 + g;
                    *(__nv_bfloat162*)(H1 + r0 * SH + c0) = __floats2bfloat162_rn(
                        fmaxf(acc[mi][ni][0] + bb0, 0.f), fmaxf(acc[mi][ni][1] + bb1, 0.f));
                    *(__nv_bfloat162*)(H1 + (r0 + 8) * SH + c0) = __floats2bfloat162_rn(
                        fmaxf(acc[mi][ni][2] + bb0, 0.f), fmaxf(acc[mi][ni][3] + bb1, 0.f));
                }
        }
    }
    __syncthreads();   // H1 published

    // ---- stage 2: GEMM2 (H1 @ W2) -> H2 ; one item/warp, mi=4, NI=4, K=304 ----
    {
        float acc[4][4][4];
        const int cg = warp;
        #pragma unroll
        for (int mi = 0; mi < 4; mi++)
            #pragma unroll
            for (int ni = 0; ni < 4; ni++)
                #pragma unroll
                for (int r = 0; r < 4; r++) acc[mi][ni][r] = 0.f;
        const uint32_t aBase1 = smem_u32(H1 + (lane & 15) * SH) + ((lane >> 4) * 8) * 2;
        const uint4* Bq = g_W2q + (size_t)cg * 40 * 32 + lane;
        #pragma unroll
        for (int ksp = 0; ksp < 10; ksp++) {
            uint4 bq[4];
            #pragma unroll
            for (int ni = 0; ni < 4; ni++)
                bq[ni] = __ldg(Bq + (ni * 10 + ksp) * 32);
            {   // even k-step (2*ksp)
                uint32_t a[4][4];
                const uint32_t ac = aBase1 + (ksp * 32) * 2;
                #pragma unroll
                for (int mi = 0; mi < 4; mi++)
                    asm volatile("ldmatrix.sync.aligned.m8n8.x4.shared.b16 {%0,%1,%2,%3}, [%4];\n"
                        : "=r"(a[mi][0]), "=r"(a[mi][1]), "=r"(a[mi][2]), "=r"(a[mi][3])
                        : "r"(ac + mi * 16 * SH * 2));
                #pragma unroll
                for (int mi = 0; mi < 4; mi++)
                    #pragma unroll
                    for (int ni = 0; ni < 4; ni++)
                        MMA(acc[mi][ni], a[mi], bq[ni].x, bq[ni].y);
            }
            if (ksp < 9) {   // odd k-step (2*ksp+1) ; step 19 doesn't exist (K=304)
                uint32_t a[4][4];
                const uint32_t ac = aBase1 + (ksp * 32 + 16) * 2;
                #pragma unroll
                for (int mi = 0; mi < 4; mi++)
                    asm volatile("ldmatrix.sync.aligned.m8n8.x4.shared.b16 {%0,%1,%2,%3}, [%4];\n"
                        : "=r"(a[mi][0]), "=r"(a[mi][1]), "=r"(a[mi][2]), "=r"(a[mi][3])
                        : "r"(ac + mi * 16 * SH * 2));
                #pragma unroll
                for (int mi = 0; mi < 4; mi++)
                    #pragma unroll
                    for (int ni = 0; ni < 4; ni++)
                        MMA(acc[mi][ni], a[mi], bq[ni].z, bq[ni].w);
            }
        }
        #pragma unroll
        for (int mi = 0; mi < 4; mi++)
            #pragma unroll
            for (int ni = 0; ni < 4; ni++) {
                int c0 = cg * 32 + ni * 8 + q * 2;
                float bb0 = (c0 < 300)     ? __ldg(b2 + c0)     : 0.f;
                float bb1 = (c0 + 1 < 300) ? __ldg(b2 + c0 + 1) : 0.f;
                int r0 = mi * 16 + g;
                *(__nv_bfloat162*)(H2 + r0 * SH + c0) = __floats2bfloat162_rn(
                    fmaxf(acc[mi][ni][0] + bb0, 0.f), fmaxf(acc[mi][ni][1] + bb1, 0.f));
                *(__nv_bfloat162*)(H2 + (r0 + 8) * SH + c0) = __floats2bfloat162_rn(
                    fmaxf(acc[mi][ni][2] + bb0, 0.f), fmaxf(acc[mi][ni][3] + bb1, 0.f));
            }
    }
    __syncthreads();   // H2 published

    // ---- stage 3: GEMM3 (H2 @ W3), 2mg x 5ig, NI=5, K=304, fused KL ----
    float localKL = 0.f;
    {
        float acc[2][5][4];
        const int cg = ig;
        #pragma unroll
        for (int mi = 0; mi < 2; mi++)
            #pragma unroll
            for (int ni = 0; ni < 5; ni++)
                #pragma unroll
                for (int r = 0; r < 4; r++) acc[mi][ni][r] = 0.f;
        const uint32_t aBase2 = smem_u32(H2 + (mg * 32 + (lane & 15)) * SH) + ((lane >> 4) * 8) * 2;
        const uint4* Bq = g_W3q + (size_t)cg * 50 * 32 + lane;
        #pragma unroll
        for (int ksp = 0; ksp < 10; ksp++) {
            uint4 bq[5];
            #pragma unroll
            for (int ni = 0; ni < 5; ni++)
                bq[ni] = __ldg(Bq + (ni * 10 + ksp) * 32);
            {
                uint32_t a[2][4];
                const uint32_t ac = aBase2 + (ksp * 32) * 2;
                #pragma unroll
                for (int mi = 0; mi < 2; mi++)
                    asm volatile("ldmatrix.sync.aligned.m8n8.x4.shared.b16 {%0,%1,%2,%3}, [%4];\n"
                        : "=r"(a[mi][0]), "=r"(a[mi][1]), "=r"(a[mi][2]), "=r"(a[mi][3])
                        : "r"(ac + mi * 16 * SH * 2));
                #pragma unroll
                for (int mi = 0; mi < 2; mi++)
                    #pragma unroll
                    for (int ni = 0; ni < 5; ni++)
                        MMA(acc[mi][ni], a[mi], bq[ni].x, bq[ni].y);
            }
            if (ksp < 9) {
                uint32_t a[2][4];
                const uint32_t ac = aBase2 + (ksp * 32 + 16) * 2;
                #pragma unroll
                for (int mi = 0; mi < 2; mi++)
                    asm volatile("ldmatrix.sync.aligned.m8n8.x4.shared.b16 {%0,%1,%2,%3}, [%4];\n"
                        : "=r"(a[mi][0]), "=r"(a[mi][1]), "=r"(a[mi][2]), "=r"(a[mi][3])
                        : "r"(ac + mi * 16 * SH * 2));
                #pragma unroll
                for (int mi = 0; mi < 2; mi++)
                    #pragma unroll
                    for (int ni = 0; ni < 5; ni++)
                        MMA(acc[mi][ni], a[mi], bq[ni].z, bq[ni].w);
            }
        }
        #pragma unroll
        for (int mi = 0; mi < 2; mi++)
            #pragma unroll
            for (int ni = 0; ni < 5; ni++) {
                int c0 = cg * 40 + ni * 8 + q * 2;       // 0..199
                int r0 = mBase + mg * 32 + mi * 16 + g;
                float bb0 = __ldg(b3 + c0), bb1 = __ldg(b3 + c0 + 1);
                #pragma unroll
                for (int h = 0; h < 2; h++) {
                    if (r0 + h * 8 >= nEdges) continue;
                    float v0 = acc[mi][ni][h * 2]     + bb0;
                    float v1 = acc[mi][ni][h * 2 + 1] + bb1;
                    localKL += (c0 < 100) ? 0.5f * (v0 * v0 + v1 * v1)
                                          : 0.5f * ((__expf(v0) - v0 - 1.f)
                                                  + (__expf(v1) - v1 - 1.f));
                }
            }
    }

    // ---- block reduce + atomic ----
    #pragma unroll
    for (int o = 16; o > 0; o >>= 1) localKL += __shfl_xor_sync(0xffffffffu, localKL, o);
    if (lane == 0) red[warp] = localKL;
    __syncthreads();
    if (t == 0) {
        float s = 0.f;
        #pragma unroll
        for (int w = 0; w < 10; w++) s += red[w];
        atomicAdd(&g_acc[1], (double)s);
    }
}

__global__ void k_finalize(float* out, int nNodes, int nEdges) {
    out[0] = (float)(g_acc[0] / (double)nNodes + g_acc[1] / (double)nEdges);
}

extern "C" void kernel_launch(void* const* d_in, const int* in_sizes, int n_in,
                              void* d_out, int out_size) {
    const float* x   = (const float*)d_in[0];
    const int*   ei  = (const int*)  d_in[1];
    const float* y   = (const float*)d_in[2];
    const float* tgt = (const float*)d_in[3];
    const float* W1  = (const float*)d_in[4];
    const float* b1  = (const float*)d_in[5];
    const float* W2  = (const float*)d_in[6];
    const float* b2  = (const float*)d_in[7];
    const float* W3  = (const float*)d_in[8];
    const float* b3  = (const float*)d_in[9];
    float* out = (float*)d_out;

    const int nNodes = in_sizes[0] / 6;
    const int nEdges = in_sizes[1] / 2;
    const int nY     = in_sizes[2];

    cudaFuncSetAttribute(k_fused, cudaFuncAttributeMaxDynamicSharedMemorySize, SMEM_BYTES);

    k_zero<<<1, 1>>>();
    k_base<<<128, 256>>>(y, tgt, nY);
    k_prep<<<(12800 + 255) / 256, 256>>>(W1, W2, W3);
    k_fused<<<(nEdges + BM - 1) / BM, NTHR, SMEM_BYTES>>>(x, ei, b1, b2, b3, nEdges);
    k_finalize<<<1, 1>>>(out, nNodes, nEdges);
}